// round 1
// baseline (speedup 1.0000x reference)
#include <cuda_runtime.h>

// YOLOv1 loss, HBM-bound reduction.
// pred/target: (B, 7, 7, 30) fp32 flattened; out: 5 fp32 scalars
// (total, loc_loss, conf_loss_obj, conf_loss_no_obj, cls_loss).

#define TPB   128   // threads per block
#define TILE  128   // cells per tile (one cell per thread in compute phase)
#define PAD   31    // smem row stride in floats (odd -> conflict-free LDS)
#define MAXBLOCKS 8192

__device__ float g_partials[MAXBLOCKS * 5];

__device__ __forceinline__ float iou_fn(float bx, float by, float bw, float bh,
                                        float tx, float ty, float tw, float th)
{
    float ax1 = bx - bw * 0.5f, ay1 = by - bh * 0.5f;
    float ax2 = bx + bw * 0.5f, ay2 = by + bh * 0.5f;
    float cx1 = tx - tw * 0.5f, cy1 = ty - th * 0.5f;
    float cx2 = tx + tw * 0.5f, cy2 = ty + th * 0.5f;
    float iw = fmaxf(fminf(ax2, cx2) - fmaxf(ax1, cx1), 0.0f);
    float ih = fmaxf(fminf(ay2, cy2) - fmaxf(ay1, cy1), 0.0f);
    float inter = iw * ih;
    float uni = bw * bh + tw * th - inter;
    return inter / fmaxf(uni, 1e-10f);
}

__global__ __launch_bounds__(TPB)
void yolo_loss_kernel(const float* __restrict__ pred,
                      const float* __restrict__ target,
                      int n_cells)
{
    __shared__ float sp[TILE * PAD];
    __shared__ float st[TILE * PAD];
    __shared__ float sred[5][TPB / 32];

    const int tid = threadIdx.x;

    float acc0 = 0.f, acc1 = 0.f, acc2 = 0.f, acc3 = 0.f, acc4 = 0.f;

    for (long long tile0 = (long long)blockIdx.x * TILE; tile0 < n_cells;
         tile0 += (long long)gridDim.x * TILE)
    {
        int valid = (int)min((long long)TILE, (long long)n_cells - tile0);
        const float* pg = pred   + tile0 * 30;
        const float* tg = target + tile0 * 30;

        if (valid == TILE) {
            // Fully coalesced float4 stream: thread i loads float4 #i of the tile.
            const float4* p4 = (const float4*)pg;
            const float4* t4 = (const float4*)tg;
            #pragma unroll 1
            for (int i = tid; i < TILE * 30 / 4; i += TPB) {
                float4 v = p4[i];
                float4 w = t4[i];
                int e = 4 * i;
                int r = e / 30;
                int c = e - r * 30;
                float pv[4] = {v.x, v.y, v.z, v.w};
                float tv[4] = {w.x, w.y, w.z, w.w};
                #pragma unroll
                for (int k = 0; k < 4; k++) {
                    sp[r * PAD + c] = pv[k];
                    st[r * PAD + c] = tv[k];
                    if (++c == 30) { c = 0; ++r; }
                }
            }
        } else {
            for (int i = tid; i < valid * 30; i += TPB) {
                int r = i / 30, c = i - r * 30;
                sp[r * PAD + c] = pg[i];
                st[r * PAD + c] = tg[i];
            }
        }
        __syncthreads();

        if (tid < valid) {
            const float* P = sp + tid * PAD;
            const float* T = st + tid * PAD;

            float t4v  = T[4];
            float objf = (t4v == 1.0f) ? 1.0f : 0.0f;
            float noobjf = 1.0f - objf;

            float tx = T[0], ty = T[1], tw = T[2], th = T[3];
            float i0 = iou_fn(P[0], P[1], P[2], P[3], tx, ty, tw, th);
            float i1 = iou_fn(P[5], P[6], P[7], P[8], tx, ty, tw, th);

            bool b0 = (i0 > i1);   // jnp.where(iou0 > iou1, 0, 1): ties pick box1
            float wx = b0 ? P[0] : P[5];
            float wy = b0 ? P[1] : P[6];
            float ww = b0 ? P[2] : P[7];
            float wh = b0 ? P[3] : P[8];
            float wc = b0 ? P[4] : P[9];
            float wiou = fmaxf(i0, i1);

            float dx = wx - tx, dy = wy - ty;
            float dw = sqrtf(ww) - sqrtf(tw);
            float dh = sqrtf(wh) - sqrtf(th);
            acc0 += (dx * dx + dy * dy + dw * dw + dh * dh) * objf;

            float dc = wc - wiou;
            acc1 += dc * dc * objf;

            float d4 = P[4] - t4v;
            float d9 = P[9] - T[9];
            acc2 += (d4 * d4 + d9 * d9) * noobjf;

            // cross-entropy with log_softmax over pred[10:30]
            float m = -1e30f;
            #pragma unroll
            for (int c = 0; c < 20; c++) m = fmaxf(m, P[10 + c]);
            float s = 0.0f;
            #pragma unroll
            for (int c = 0; c < 20; c++) s += __expf(P[10 + c] - m);
            float tm = -1e30f; int targc = 0;
            #pragma unroll
            for (int c = 0; c < 20; c++) {
                float v = T[10 + c];
                if (v > tm) { tm = v; targc = c; }   // first-occurrence argmax
            }
            float ce = m + __logf(s) - P[10 + targc];
            acc3 += ce * objf;
            acc4 += objf;
        }
        __syncthreads();
    }

    // Deterministic in-block reduction: warp shuffle, then warp0 over smem.
    const unsigned mask = 0xffffffffu;
    #pragma unroll
    for (int off = 16; off; off >>= 1) {
        acc0 += __shfl_down_sync(mask, acc0, off);
        acc1 += __shfl_down_sync(mask, acc1, off);
        acc2 += __shfl_down_sync(mask, acc2, off);
        acc3 += __shfl_down_sync(mask, acc3, off);
        acc4 += __shfl_down_sync(mask, acc4, off);
    }
    int lane = tid & 31, w = tid >> 5;
    if (lane == 0) {
        sred[0][w] = acc0; sred[1][w] = acc1; sred[2][w] = acc2;
        sred[3][w] = acc3; sred[4][w] = acc4;
    }
    __syncthreads();
    if (tid == 0) {
        float r0 = 0.f, r1 = 0.f, r2 = 0.f, r3 = 0.f, r4 = 0.f;
        #pragma unroll
        for (int i = 0; i < TPB / 32; i++) {
            r0 += sred[0][i]; r1 += sred[1][i]; r2 += sred[2][i];
            r3 += sred[3][i]; r4 += sred[4][i];
        }
        g_partials[blockIdx.x * 5 + 0] = r0;
        g_partials[blockIdx.x * 5 + 1] = r1;
        g_partials[blockIdx.x * 5 + 2] = r2;
        g_partials[blockIdx.x * 5 + 3] = r3;
        g_partials[blockIdx.x * 5 + 4] = r4;
    }
}

__global__ __launch_bounds__(256)
void yolo_final_kernel(int nblocks, float* __restrict__ out, float invB)
{
    __shared__ float s[5][256];
    const int tid = threadIdx.x;
    float a[5] = {0.f, 0.f, 0.f, 0.f, 0.f};
    for (int j = tid; j < nblocks; j += 256) {
        #pragma unroll
        for (int k = 0; k < 5; k++) a[k] += g_partials[j * 5 + k];
    }
    #pragma unroll
    for (int k = 0; k < 5; k++) s[k][tid] = a[k];
    __syncthreads();
    for (int stride = 128; stride > 0; stride >>= 1) {
        if (tid < stride) {
            #pragma unroll
            for (int k = 0; k < 5; k++) s[k][tid] += s[k][tid + stride];
        }
        __syncthreads();
    }
    if (tid == 0) {
        float loc  = s[0][0];
        float cobj = s[1][0];
        float cno  = s[2][0];
        float ce   = s[3][0];
        float nobj = s[4][0];
        float n    = fmaxf(nobj, 1.0f);
        float cls  = ce / n;
        out[0] = (5.0f * loc + cobj + 0.5f * cno + cls) * invB;
        out[1] = loc;
        out[2] = cobj;
        out[3] = cno;
        out[4] = cls;
    }
}

extern "C" void kernel_launch(void* const* d_in, const int* in_sizes, int n_in,
                              void* d_out, int out_size)
{
    const float* pred   = (const float*)d_in[0];
    const float* target = (const float*)d_in[1];
    int n_elems = in_sizes[0];
    int n_cells = n_elems / 30;

    int grid = (n_cells + TILE - 1) / TILE;
    if (grid > MAXBLOCKS) grid = MAXBLOCKS;

    yolo_loss_kernel<<<grid, TPB>>>(pred, target, n_cells);

    float invB = 49.0f / (float)n_cells;   // B = n_cells / 49
    yolo_final_kernel<<<1, 256>>>(grid, (float*)d_out, invB);
}

// round 2
// speedup vs baseline: 1.5301x; 1.5301x over previous
#include <cuda_runtime.h>
#include <cstdint>

// YOLOv1 loss — single fused kernel, cp.async 2-stage pipeline, ticket finalize.
// pred/target: (B, 7, 7, 30) fp32; out: 5 fp32 scalars.

#define TPB   128
#define TILE  128
#define NF4   (TILE * 30 / 4)          // 960 float4 per tensor per tile
#define STAGE_BYTES (2 * NF4 * 16)     // pred+target, one stage = 30720 B
#define SMEM_BYTES  (2 * STAGE_BYTES)  // 2 stages = 61440 B
#define GRID_MAX 1024

__device__ float g_partials[GRID_MAX * 5];
__device__ unsigned int g_ticket = 0;

__device__ __forceinline__ void cp16(unsigned dst, const void* src) {
    asm volatile("cp.async.cg.shared.global [%0], [%1], 16;" :: "r"(dst), "l"(src));
}

__device__ __forceinline__ float iou_fn(float bx, float by, float bw, float bh,
                                        float tx, float ty, float tw, float th)
{
    float ax1 = bx - bw * 0.5f, ay1 = by - bh * 0.5f;
    float ax2 = bx + bw * 0.5f, ay2 = by + bh * 0.5f;
    float cx1 = tx - tw * 0.5f, cy1 = ty - th * 0.5f;
    float cx2 = tx + tw * 0.5f, cy2 = ty + th * 0.5f;
    float iw = fmaxf(fminf(ax2, cx2) - fmaxf(ax1, cx1), 0.0f);
    float ih = fmaxf(fminf(ay2, cy2) - fmaxf(ay1, cy1), 0.0f);
    float inter = iw * ih;
    float uni = bw * bh + tw * th - inter;
    return inter / fmaxf(uni, 1e-10f);
}

extern __shared__ float4 dynbuf[];   // [2 stages][2 tensors][NF4]

__global__ __launch_bounds__(TPB)
void yolo_fused_kernel(const float* __restrict__ pred,
                       const float* __restrict__ target,
                       int n_cells, float invB,
                       float* __restrict__ out)
{
    const int tid = threadIdx.x;
    const int nb  = gridDim.x;
    const int ntiles = (n_cells + TILE - 1) / TILE;

    float acc0 = 0.f, acc1 = 0.f, acc2 = 0.f, acc3 = 0.f, acc4 = 0.f;

    // ---- issue loads for one tile into stage s (one commit_group per call) ----
    auto issue = [&](int tile, int s) {
        long long c0 = (long long)tile * TILE;
        int valid = (int)min((long long)TILE, (long long)n_cells - c0);
        const float* pg = pred   + c0 * 30;
        const float* tg = target + c0 * 30;
        float* sp = (float*)(dynbuf + (size_t)s * 2 * NF4);
        float* st = sp + NF4 * 4;
        if (valid == TILE) {
            unsigned bp = (unsigned)__cvta_generic_to_shared(sp);
            unsigned bt = (unsigned)__cvta_generic_to_shared(st);
            #pragma unroll 4
            for (int i = tid; i < NF4; i += TPB) {
                cp16(bp + 16u * i, ((const float4*)pg) + i);
                cp16(bt + 16u * i, ((const float4*)tg) + i);
            }
        } else {
            for (int i = tid; i < valid * 30; i += TPB) {
                sp[i] = pg[i];
                st[i] = tg[i];
            }
        }
        asm volatile("cp.async.commit_group;");
    };

    int t = blockIdx.x;
    if (t < ntiles) issue(t, 0);

    int s = 0;
    for (; t < ntiles; t += nb, s ^= 1) {
        long long c0 = (long long)t * TILE;
        int valid = (int)min((long long)TILE, (long long)n_cells - c0);

        int tn = t + nb;
        if (tn < ntiles) {
            issue(tn, s ^ 1);
            asm volatile("cp.async.wait_group 1;");
        } else {
            asm volatile("cp.async.wait_group 0;");
        }
        __syncthreads();

        if (tid < valid) {
            const float* sp = (const float*)(dynbuf + (size_t)s * 2 * NF4);
            const float* P = sp + tid * 30;
            const float* T = sp + NF4 * 4 + tid * 30;

            float t4v  = T[4];
            float objf = (t4v == 1.0f) ? 1.0f : 0.0f;
            float noobjf = 1.0f - objf;

            float tx = T[0], ty = T[1], tw = T[2], th = T[3];
            float i0 = iou_fn(P[0], P[1], P[2], P[3], tx, ty, tw, th);
            float i1 = iou_fn(P[5], P[6], P[7], P[8], tx, ty, tw, th);

            bool b0 = (i0 > i1);   // ties -> box 1 (matches jnp.where)
            float wx = b0 ? P[0] : P[5];
            float wy = b0 ? P[1] : P[6];
            float ww = b0 ? P[2] : P[7];
            float wh = b0 ? P[3] : P[8];
            float wc = b0 ? P[4] : P[9];
            float wiou = fmaxf(i0, i1);

            float dx = wx - tx, dy = wy - ty;
            float dw = sqrtf(ww) - sqrtf(tw);
            float dh = sqrtf(wh) - sqrtf(th);
            acc0 += (dx * dx + dy * dy + dw * dw + dh * dh) * objf;

            float dc = wc - wiou;
            acc1 += dc * dc * objf;

            float d4 = P[4] - t4v;
            float d9 = P[9] - T[9];
            acc2 += (d4 * d4 + d9 * d9) * noobjf;

            float m = -1e30f;
            #pragma unroll
            for (int c = 0; c < 20; c++) m = fmaxf(m, P[10 + c]);
            float sum = 0.0f;
            #pragma unroll
            for (int c = 0; c < 20; c++) sum += __expf(P[10 + c] - m);
            float tm = -1e30f; int targc = 0;
            #pragma unroll
            for (int c = 0; c < 20; c++) {
                float v = T[10 + c];
                if (v > tm) { tm = v; targc = c; }  // first-occurrence argmax
            }
            float ce = m + __logf(sum) - P[10 + targc];
            acc3 += ce * objf;
            acc4 += objf;
        }
        __syncthreads();
    }

    // ---- deterministic in-block reduction ----
    __shared__ float sred[5][TPB / 32];
    const unsigned mask = 0xffffffffu;
    #pragma unroll
    for (int off = 16; off; off >>= 1) {
        acc0 += __shfl_down_sync(mask, acc0, off);
        acc1 += __shfl_down_sync(mask, acc1, off);
        acc2 += __shfl_down_sync(mask, acc2, off);
        acc3 += __shfl_down_sync(mask, acc3, off);
        acc4 += __shfl_down_sync(mask, acc4, off);
    }
    int lane = tid & 31, w = tid >> 5;
    if (lane == 0) {
        sred[0][w] = acc0; sred[1][w] = acc1; sred[2][w] = acc2;
        sred[3][w] = acc3; sred[4][w] = acc4;
    }
    __syncthreads();
    if (tid == 0) {
        float r0 = 0.f, r1 = 0.f, r2 = 0.f, r3 = 0.f, r4 = 0.f;
        #pragma unroll
        for (int i = 0; i < TPB / 32; i++) {
            r0 += sred[0][i]; r1 += sred[1][i]; r2 += sred[2][i];
            r3 += sred[3][i]; r4 += sred[4][i];
        }
        g_partials[blockIdx.x * 5 + 0] = r0;
        g_partials[blockIdx.x * 5 + 1] = r1;
        g_partials[blockIdx.x * 5 + 2] = r2;
        g_partials[blockIdx.x * 5 + 3] = r3;
        g_partials[blockIdx.x * 5 + 4] = r4;
    }

    // ---- ticket: last finishing block does the final reduction ----
    __shared__ int amLast;
    __threadfence();
    __syncthreads();
    if (tid == 0) {
        unsigned tk = atomicAdd(&g_ticket, 1u);
        amLast = (tk == (unsigned)(nb - 1));
    }
    __syncthreads();

    if (amLast) {
        float a0 = 0.f, a1 = 0.f, a2 = 0.f, a3 = 0.f, a4 = 0.f;
        for (int j = tid; j < nb; j += TPB) {
            a0 += g_partials[j * 5 + 0];
            a1 += g_partials[j * 5 + 1];
            a2 += g_partials[j * 5 + 2];
            a3 += g_partials[j * 5 + 3];
            a4 += g_partials[j * 5 + 4];
        }
        #pragma unroll
        for (int off = 16; off; off >>= 1) {
            a0 += __shfl_down_sync(mask, a0, off);
            a1 += __shfl_down_sync(mask, a1, off);
            a2 += __shfl_down_sync(mask, a2, off);
            a3 += __shfl_down_sync(mask, a3, off);
            a4 += __shfl_down_sync(mask, a4, off);
        }
        if (lane == 0) {
            sred[0][w] = a0; sred[1][w] = a1; sred[2][w] = a2;
            sred[3][w] = a3; sred[4][w] = a4;
        }
        __syncthreads();
        if (tid == 0) {
            float loc = 0.f, cobj = 0.f, cno = 0.f, ce = 0.f, nobj = 0.f;
            #pragma unroll
            for (int i = 0; i < TPB / 32; i++) {
                loc += sred[0][i]; cobj += sred[1][i]; cno += sred[2][i];
                ce  += sred[3][i]; nobj += sred[4][i];
            }
            float n   = fmaxf(nobj, 1.0f);
            float cls = ce / n;
            out[0] = (5.0f * loc + cobj + 0.5f * cno + cls) * invB;
            out[1] = loc;
            out[2] = cobj;
            out[3] = cno;
            out[4] = cls;
            __threadfence();
            g_ticket = 0;   // reset for next graph replay (deterministic)
        }
    }
}

extern "C" void kernel_launch(void* const* d_in, const int* in_sizes, int n_in,
                              void* d_out, int out_size)
{
    const float* pred   = (const float*)d_in[0];
    const float* target = (const float*)d_in[1];
    int n_elems = in_sizes[0];
    int n_cells = n_elems / 30;

    static bool configured = false;
    if (!configured) {
        cudaFuncSetAttribute(yolo_fused_kernel,
                             cudaFuncAttributeMaxDynamicSharedMemorySize,
                             SMEM_BYTES);
        configured = true;
    }

    int ntiles = (n_cells + TILE - 1) / TILE;
    int grid = 444;                       // 148 SMs x 3 CTAs (61.4 KB smem each)
    if (grid > ntiles) grid = ntiles;
    if (grid > GRID_MAX) grid = GRID_MAX;

    float invB = 49.0f / (float)n_cells;  // B = n_cells / 49

    yolo_fused_kernel<<<grid, TPB, SMEM_BYTES>>>(pred, target, n_cells, invB,
                                                 (float*)d_out);
}